// round 15
// baseline (speedup 1.0000x reference)
#include <cuda_runtime.h>
#include <math.h>

#define B_  2
#define L_  256
#define DM_ 256
#define H_  8
#define DH_ 32
#define T_  4
#define NK_ 4
#define M_  128                 // gaussian terms per (h,t)
#define NPAIR 32896             // L*(L+1)/2, i<=j pairs
#define NTAB 2048
// narrow threshold: sigma < 0.02  <=>  A < -log2e/(2*0.02^2)
#define A_TH (-1803.3688f)
#define KTS 260                 // attn Kt/Xt row stride
#define WSS 36                  // qkv gemm smem row stride (floats, 16B-aligned)
#define PSS 260                 // proj gemm smem row stride (floats, 16B-aligned)

// ---------------- scratch (device globals; no allocation allowed) -------------
__device__ float  g_Q[B_*H_*L_*DH_];
__device__ float  g_K[B_*H_*L_*DH_];
__device__ float  g_V[B_*H_*L_*DH_];
__device__ float4 g_nwP[H_*T_*M_];           // narrow (exact) rel terms, compact per (h,t)
__device__ int    g_ncnt[H_*T_];
__device__ float2 g_tab2[H_*T_*NTAB];        // (f(e), f(e+1)) pairs
__device__ float  g_gabs[B_*H_*L_];
__device__ float  g_grel[B_*H_*L_*L_];
__device__ float  g_outh[B_*L_*DM_];

__device__ __forceinline__ float ex2f(float x){
    float r; asm("ex2.approx.ftz.f32 %0, %1;" : "=f"(r) : "f"(x)); return r;
}

// ============ qkv smem GEMM tile: 32 rows x 64 o, 256 threads =================
// C[rbase+r][obase+o] = sum_k Xg[rbase+r][k] * Wg[obase+o][k]   (W row-major [o][k])
// Thread (o4=tid&15, rgrp=tid>>4): rows {2*rgrp, 2*rgrp+1}, o = o4 + 16*c (c=0..3).
// smem: xs[32][WSS] (1152 f) + ws[64][WSS] (2304 f) = 3456 floats (13.8KB)
__device__ __forceinline__ void gemm_tile_32x64(
    const float* __restrict__ Xg, const float* __restrict__ Wg,
    int rbase, int obase, int tid, float* sm, float acc[2][4])
{
    float* xs = sm;                    // [32][WSS]
    float* ws = sm + 32*WSS;           // [64][WSS]
    int o4 = tid & 15, rgrp = tid >> 4;
    int r0 = rgrp*2;
    #pragma unroll
    for (int r=0;r<2;r++)
        #pragma unroll
        for (int c=0;c<4;c++) acc[r][c] = 0.f;

    for (int kt = 0; kt < 8; kt++){
        {   // x tile: 32 rows x 32 k = 256 float4, one per thread (coalesced)
            int r = tid >> 3, kk4 = tid & 7;
            float4 xv = *(const float4*)&Xg[(rbase+r)*DM_ + kt*32 + kk4*4];
            *(float4*)&xs[r*WSS + kk4*4] = xv;
        }
        #pragma unroll
        for (int p2 = 0; p2 < 2; p2++){  // w tile: 64 rows x 32 k = 512 float4
            int v = tid + p2*256;
            int oo = v >> 3, kk4 = v & 7;
            float4 wv = *(const float4*)&Wg[(obase+oo)*DM_ + kt*32 + kk4*4];
            *(float4*)&ws[oo*WSS + kk4*4] = wv;
        }
        __syncthreads();
        #pragma unroll
        for (int kk4 = 0; kk4 < 8; kk4++){
            float4 xa = *(const float4*)&xs[r0*WSS + kk4*4];
            float4 xb = *(const float4*)&xs[(r0+1)*WSS + kk4*4];
            #pragma unroll
            for (int c = 0; c < 4; c++){
                float4 w = *(const float4*)&ws[(o4+16*c)*WSS + kk4*4];
                acc[0][c] = fmaf(xa.x,w.x,acc[0][c]);
                acc[0][c] = fmaf(xa.y,w.y,acc[0][c]);
                acc[0][c] = fmaf(xa.z,w.z,acc[0][c]);
                acc[0][c] = fmaf(xa.w,w.w,acc[0][c]);
                acc[1][c] = fmaf(xb.x,w.x,acc[1][c]);
                acc[1][c] = fmaf(xb.y,w.y,acc[1][c]);
                acc[1][c] = fmaf(xb.z,w.z,acc[1][c]);
                acc[1][c] = fmaf(xb.w,w.w,acc[1][c]);
            }
        }
        __syncthreads();
    }
}

// ========== prep: qkv (bx<192) | rel-table (<448) | gabs (<464) ===============
// qkv (long blocks) scheduled FIRST so short table/gabs blocks backfill the tail.
__global__ __launch_bounds__(256) void prep_kernel(
                            const float* __restrict__ mu_r, const float* __restrict__ sg_r,
                            const float* __restrict__ w_r,
                            const float* __restrict__ mu_a, const float* __restrict__ sg_a,
                            const float* __restrict__ w_a,
                            const float* __restrict__ tarr,
                            const float* __restrict__ x,
                            const float* __restrict__ WQ, const float* __restrict__ WK,
                            const float* __restrict__ WV)
{
    __shared__ __align__(16) float sm[32*WSS + 64*WSS];     // 3456 floats
    int bx = blockIdx.x, tid = threadIdx.x;

    if (bx < 192){
        // ---- qkv GEMM: 192 blocks = 3 mats x 16 rowblocks x 4 ocols ----
        int mat = bx / 64, rem = bx % 64;
        int rbase = (rem >> 2) * 32;
        int obase = (rem & 3) * 64;
        const float* Wm = (mat==0)?WQ:(mat==1)?WK:WV;
        float acc[2][4];
        gemm_tile_32x64(x, Wm, rbase, obase, tid, sm, acc);
        float* dst = (mat==0)?g_Q:(mat==1)?g_K:g_V;
        int o4 = tid & 15, rgrp = tid >> 4;
        #pragma unroll
        for (int r=0;r<2;r++){
            int rg = rbase + rgrp*2 + r;
            int b = rg >> 8, l = rg & 255;
            #pragma unroll
            for (int c=0;c<4;c++){
                int o = obase + o4 + 16*c;
                int h = o >> 5, d = o & 31;
                dst[((b*H_+h)*L_+l)*DH_ + d] = acc[r][c];
            }
        }
    } else if (bx < 448){
        int idx = bx - 192;
        int cx = idx & 7, y = idx >> 3;             // y = h*T+tt
        int h = y >> 2, tt = y & 3;
        float4* Ps = (float4*)sm;                   // 128 float4
        float*  sv = sm + 512;                      // 257 floats
        if (tid < M_){
            int d = tid >> 2, k = tid & 3;
            int src = ((h*DH_+d)*T_+tt)*NK_+k;
            float s = sg_r[src];
            float A = -1.4426950408889634f / (2.0f*s*s);
            Ps[tid] = make_float4(mu_r[src], A, w_r[src], 0.f);
        }
        __syncthreads();
        int e0 = cx*256;
        for (int ee = tid; ee < 257; ee += 256){
            float u = (float)(e0+ee) * (1.0f/NTAB);
            float a0=0.f,a1=0.f,a2=0.f,a3=0.f;
            #pragma unroll 1
            for (int m=0;m<M_;m+=4){
                float4 p0=Ps[m],p1=Ps[m+1],p2=Ps[m+2],p3=Ps[m+3];
                float w0=(p0.y>=A_TH)?p0.z:0.f; float d0=u-p0.x;
                float w1=(p1.y>=A_TH)?p1.z:0.f; float d1=u-p1.x;
                float w2=(p2.y>=A_TH)?p2.z:0.f; float d2=u-p2.x;
                float w3=(p3.y>=A_TH)?p3.z:0.f; float d3=u-p3.x;
                a0 = fmaf(w0, ex2f(d0*d0*p0.y), a0);
                a1 = fmaf(w1, ex2f(d1*d1*p1.y), a1);
                a2 = fmaf(w2, ex2f(d2*d2*p2.y), a2);
                a3 = fmaf(w3, ex2f(d3*d3*p3.y), a3);
            }
            sv[ee] = (a0+a1)+(a2+a3);
        }
        __syncthreads();
        if (e0 + tid < NTAB)
            g_tab2[y*NTAB + e0 + tid] = make_float2(sv[tid], sv[tid+1]);
        if (cx == 0 && tid < 32){
            int base = 0;
            #pragma unroll
            for (int g=0; g<4; g++){
                float4 p = Ps[g*32 + tid];
                bool narrow = (p.y < A_TH);
                unsigned bal = __ballot_sync(0xffffffffu, narrow);
                int pos = __popc(bal & ((1u<<tid)-1u));
                if (narrow) g_nwP[y*M_ + base + pos] = p;
                base += __popc(bal);
            }
            if (tid == 0) g_ncnt[y] = base;
        }
    } else {
        int y = bx - 448; int h = y >> 1, b = y & 1;
        float4* Ps = (float4*)sm;                   // 512 float4
        for (int pass=0; pass<2; pass++){
            int m2 = pass*256 + tid;
            int tt = m2 >> 7, m = m2 & 127;
            int d = m >> 2, k = m & 3;
            int src = ((h*DH_+d)*T_+tt)*NK_+k;
            float s = sg_a[src];
            float A = -1.4426950408889634f / (2.0f*s*s);
            Ps[m2] = make_float4(mu_a[src], A, w_a[src], 0.f);
        }
        __syncthreads();
        int p = tid;
        float4 tv = *(const float4*)&tarr[(b*L_+p)*T_];
        float us[4] = {tv.x,tv.y,tv.z,tv.w};
        float acc = 0.f;
        #pragma unroll
        for (int tt=0;tt<T_;tt++){
            float u = us[tt];
            const float4* P = Ps + tt*M_;
            #pragma unroll 4
            for (int m=0;m<M_;m++){
                float4 pr = P[m];
                float d = u - pr.x;
                acc = fmaf(pr.z, ex2f(d*d*pr.y), acc);
            }
        }
        g_gabs[(b*H_+h)*L_+p] = acc * (1.0f/DH_);
    }
}

// ================= grel: 2056 blocks, warp = 32 pairs, uniform h ==============
__global__ __launch_bounds__(256) void grel_kernel(const float* __restrict__ tarr)
{
    __shared__ int ncs[H_*T_];
    int bx = blockIdx.x, tid = threadIdx.x;
    int b  = bx / 1028;
    int pb = bx % 1028;
    if (tid < 32) ncs[tid] = g_ncnt[tid];
    __syncthreads();

    int p = pb*32 + (tid & 31);                 // < 1028*32 = NPAIR exactly
    int h = tid >> 5;
    float disc = sqrtf((float)((2*L_+1)*(2*L_+1) - 8*p));
    int i = (int)((2.0f*L_+1.0f - disc)*0.5f);
    if (i < 0) i = 0; if (i > L_-1) i = L_-1;
    #define TBASE(ii) ((ii)*L_ - ((ii)*((ii)-1))/2)
    while (i+1 <= L_ && TBASE(i+1) <= p) ++i;
    while (TBASE(i) > p) --i;
    int j = i + (p - TBASE(i));
    #undef TBASE

    float4 ti = *(const float4*)&tarr[(b*L_+i)*T_];
    float4 tj = *(const float4*)&tarr[(b*L_+j)*T_];
    float us[4] = {fabsf(ti.x-tj.x), fabsf(ti.y-tj.y), fabsf(ti.z-tj.z), fabsf(ti.w-tj.w)};

    float acc = 0.f;
    #pragma unroll
    for (int tt=0;tt<4;tt++){
        float f = us[tt] * (float)NTAB;
        int ib = (int)f;
        if (ib > NTAB-1) ib = NTAB-1;
        float fr = f - (float)ib;
        float2 v = __ldg(&g_tab2[(h*T_+tt)*NTAB + ib]);
        acc += fmaf(fr, v.y - v.x, v.x);
    }
    #pragma unroll
    for (int tt=0;tt<4;tt++){
        int c = ncs[h*T_+tt];
        const float4* np = g_nwP + (h*T_+tt)*M_;
        for (int m=0; m<c; m++){
            float4 pr = __ldg(&np[m]);
            float d = us[tt] - pr.x;
            acc = fmaf(pr.z, ex2f(d*d*pr.y), acc);
        }
    }
    acc *= (1.0f/DH_);
    g_grel[((b*H_+h)*L_+i)*L_+j] = acc;
    g_grel[((b*H_+h)*L_+j)*L_+i] = acc;
}

// ================= fused attention: 16 rows/block, 256 threads ================
__global__ __launch_bounds__(256,2) void attn_kernel(const float* __restrict__ x,
                            const float* __restrict__ alpha,
                            const float* __restrict__ beta,
                            const float* __restrict__ gamma)
{
    extern __shared__ float sm[];
    float* Kt    = sm;              // [32][KTS]  (phase 1)
    float* Xt    = sm + 8320;       // [32][KTS]
    float* Qt    = sm + 16640;      // [32][16]
    float* Vs    = sm + 17152;      // [256][32]
    float* probs = sm;              // [16][256]  (phase 2, aliases Kt)

    int tid = threadIdx.x;
    int i0 = blockIdx.x*16, h = blockIdx.y, b = blockIdx.z;
    const float4* Kg4 = (const float4*)(g_K + (b*H_+h)*L_*DH_);
    const float4* Vg4 = (const float4*)(g_V + (b*H_+h)*L_*DH_);

    int lane = tid & 31, wid = tid >> 5;
    int r0 = (wid & 3)*4;                          // 4 rows of 16
    int jb = (wid >> 2)*128 + lane*4;              // 4 cols of 256

    // prefetch per-head scalars + gabs for this warp's rows (hidden under loads/FMA)
    float al2 = 2.0f*__ldg(&alpha[h]), be = __ldg(&beta[h]), ga = __ldg(&gamma[h]);
    float gi_pre[4];
    #pragma unroll
    for (int r=0;r<4;r++) gi_pre[r] = __ldg(&g_gabs[(b*H_+h)*L_ + i0 + r0 + r]);

    for (int v = tid; v < 2048; v += 256){
        int j = v >> 3, d4 = (v & 7)*4;
        float4 kq = Kg4[v];
        Kt[(d4+0)*KTS+j]=kq.x; Kt[(d4+1)*KTS+j]=kq.y; Kt[(d4+2)*KTS+j]=kq.z; Kt[(d4+3)*KTS+j]=kq.w;
        float4 vv = Vg4[v];
        *(float4*)&Vs[j*DH_ + d4] = vv;
        float4 xv = *(const float4*)&x[(b*L_+j)*DM_ + h*DH_ + d4];
        Xt[(d4+0)*KTS+j]=xv.x; Xt[(d4+1)*KTS+j]=xv.y; Xt[(d4+2)*KTS+j]=xv.z; Xt[(d4+3)*KTS+j]=xv.w;
    }
    if (tid < 128){
        int r = tid >> 3, d4 = (tid & 7)*4;
        float4 q = *(const float4*)&g_Q[((b*H_+h)*L_ + i0 + r)*DH_ + d4];
        Qt[(d4+0)*16+r]=q.x; Qt[(d4+1)*16+r]=q.y; Qt[(d4+2)*16+r]=q.z; Qt[(d4+3)*16+r]=q.w;
    }
    __syncthreads();

    float sc[4][4], pj[4][4];
    #pragma unroll
    for (int r=0;r<4;r++){
        #pragma unroll
        for (int q=0;q<4;q++){ sc[r][q]=0.f; pj[r][q]=0.f; }
    }
    for (int d=0; d<DH_; d++){
        float4 kv  = *(const float4*)&Kt[d*KTS + jb];
        float4 xv  = *(const float4*)&Xt[d*KTS + jb];
        float4 q4  = *(const float4*)&Qt[d*16 + r0];
        float4 xi4 = *(const float4*)&Xt[d*KTS + i0 + r0];
        float qs[4]  = {q4.x,q4.y,q4.z,q4.w};
        float xis[4] = {xi4.x,xi4.y,xi4.z,xi4.w};
        float kva[4] = {kv.x,kv.y,kv.z,kv.w};
        float xva[4] = {xv.x,xv.y,xv.z,xv.w};
        #pragma unroll
        for (int r=0;r<4;r++){
            #pragma unroll
            for (int q=0;q<4;q++){
                sc[r][q] = fmaf(qs[r],  kva[q], sc[r][q]);
                pj[r][q] = fmaf(xis[r], xva[q], pj[r][q]);
            }
        }
    }

    const float invsq = 0.17677669529663687f;      // 1/sqrt(32)
    float4 ov[4];
    #pragma unroll
    for (int r=0;r<4;r++){
        int ig = i0 + r0 + r;
        float c0 = al2 * gi_pre[r];
        float4 gr = *(const float4*)&g_grel[((b*H_+h)*L_ + ig)*L_ + jb];
        ov[r].x = sc[r][0]*invsq*fmaf(pj[r][0], fmaf(be, gr.x, c0), ga);
        ov[r].y = sc[r][1]*invsq*fmaf(pj[r][1], fmaf(be, gr.y, c0), ga);
        ov[r].z = sc[r][2]*invsq*fmaf(pj[r][2], fmaf(be, gr.z, c0), ga);
        ov[r].w = sc[r][3]*invsq*fmaf(pj[r][3], fmaf(be, gr.w, c0), ga);
    }
    __syncthreads();
    #pragma unroll
    for (int r=0;r<4;r++) *(float4*)&probs[(r0+r)*L_ + jb] = ov[r];
    __syncthreads();

    float inv[2];
    #pragma unroll
    for (int rr=0; rr<2; rr++){
        int row = wid*2 + rr;
        float v[8]; float mx = -3.402823466e38f;
        #pragma unroll
        for (int k=0;k<8;k++){ v[k] = probs[row*L_ + k*32 + lane]; mx = fmaxf(mx, v[k]); }
        #pragma unroll
        for (int off=16; off; off>>=1) mx = fmaxf(mx, __shfl_xor_sync(0xffffffffu, mx, off));
        float s = 0.f;
        #pragma unroll
        for (int k=0;k<8;k++){ float e = __expf(v[k]-mx); probs[row*L_ + k*32 + lane] = e; s += e; }
        #pragma unroll
        for (int off=16; off; off>>=1) s += __shfl_xor_sync(0xffffffffu, s, off);
        inv[rr] = 1.0f/s;
    }
    __syncwarp();
    {
        int rbase = wid*2;
        float acc0 = 0.f, acc1 = 0.f;
        for (int j=0; j<L_; j+=4){
            float v0 = Vs[(j+0)*DH_ + lane];
            float v1 = Vs[(j+1)*DH_ + lane];
            float v2 = Vs[(j+2)*DH_ + lane];
            float v3 = Vs[(j+3)*DH_ + lane];
            float4 p0 = *(const float4*)&probs[(rbase+0)*L_ + j];
            float4 p1 = *(const float4*)&probs[(rbase+1)*L_ + j];
            acc0 = fmaf(p0.x, v0, acc0); acc0 = fmaf(p0.y, v1, acc0);
            acc0 = fmaf(p0.z, v2, acc0); acc0 = fmaf(p0.w, v3, acc0);
            acc1 = fmaf(p1.x, v0, acc1); acc1 = fmaf(p1.y, v1, acc1);
            acc1 = fmaf(p1.z, v2, acc1); acc1 = fmaf(p1.w, v3, acc1);
        }
        g_outh[(b*L_ + i0 + rbase+0)*DM_ + h*DH_ + lane] = acc0 * inv[0];
        g_outh[(b*L_ + i0 + rbase+1)*DM_ + h*DH_ + lane] = acc1 * inv[1];
    }
}

// ====== output projection: full-K smem GEMM, 512 threads ======================
// 32 rows x 32 o tile. Thread (o16=tid&15, row=tid>>4): o = o16 + 16*c (c=0..1).
// smem: xs[32][PSS] + ws[32][PSS] = 16640 floats = 66.56KB (dynamic)
__global__ __launch_bounds__(512) void proj_kernel(const float* __restrict__ WO,
                                                   const float* __restrict__ bO,
                                                   float* __restrict__ out)
{
    extern __shared__ __align__(16) float psm[];
    float* xs = psm;                   // [32][PSS]
    float* ws = psm + 32*PSS;          // [32][PSS]
    int bx = blockIdx.x, tid = threadIdx.x;
    int rbase = (bx >> 3) * 32;
    int obase = (bx & 7) * 32;

    #pragma unroll
    for (int p = 0; p < 4; p++){
        int v = tid + p*512;
        int r = v >> 6, c4 = v & 63;
        *(float4*)&xs[r*PSS + c4*4] = *(const float4*)&g_outh[(rbase+r)*DM_ + c4*4];
        *(float4*)&ws[r*PSS + c4*4] = *(const float4*)&WO[(obase+r)*DM_ + c4*4];
    }
    __syncthreads();

    int o16 = tid & 15, row = tid >> 4;
    const float* xr = &xs[row*PSS];
    const float* wr0 = &ws[o16*PSS];
    const float* wr1 = &ws[(o16+16)*PSS];
    float acc0 = 0.f, acc1 = 0.f;
    #pragma unroll 4
    for (int kk8 = 0; kk8 < 32; kk8++){
        float4 xa0 = *(const float4*)&xr[kk8*8];
        float4 w00 = *(const float4*)&wr0[kk8*8];
        float4 w10 = *(const float4*)&wr1[kk8*8];
        float4 xa1 = *(const float4*)&xr[kk8*8 + 4];
        float4 w01 = *(const float4*)&wr0[kk8*8 + 4];
        float4 w11 = *(const float4*)&wr1[kk8*8 + 4];
        acc0 = fmaf(xa0.x,w00.x,acc0); acc0 = fmaf(xa0.y,w00.y,acc0);
        acc0 = fmaf(xa0.z,w00.z,acc0); acc0 = fmaf(xa0.w,w00.w,acc0);
        acc1 = fmaf(xa0.x,w10.x,acc1); acc1 = fmaf(xa0.y,w10.y,acc1);
        acc1 = fmaf(xa0.z,w10.z,acc1); acc1 = fmaf(xa0.w,w10.w,acc1);
        acc0 = fmaf(xa1.x,w01.x,acc0); acc0 = fmaf(xa1.y,w01.y,acc0);
        acc0 = fmaf(xa1.z,w01.z,acc0); acc0 = fmaf(xa1.w,w01.w,acc0);
        acc1 = fmaf(xa1.x,w11.x,acc1); acc1 = fmaf(xa1.y,w11.y,acc1);
        acc1 = fmaf(xa1.z,w11.z,acc1); acc1 = fmaf(xa1.w,w11.w,acc1);
    }
    int rg = rbase + row;
    int oa = obase + o16, ob = obase + o16 + 16;
    out[rg*DM_ + oa] = acc0 + __ldg(&bO[oa]);
    out[rg*DM_ + ob] = acc1 + __ldg(&bO[ob]);
}

// ================= launch =====================================================
extern "C" void kernel_launch(void* const* d_in, const int* in_sizes, int n_in,
                              void* d_out, int out_size)
{
    const float* x   = (const float*)d_in[0];
    const float* t   = (const float*)d_in[1];
    const float* WQ  = (const float*)d_in[2];
    const float* WK  = (const float*)d_in[3];
    const float* WV  = (const float*)d_in[4];
    const float* WO  = (const float*)d_in[5];
    const float* bO  = (const float*)d_in[6];
    const float* mua = (const float*)d_in[7];
    const float* sga = (const float*)d_in[8];
    const float* wa  = (const float*)d_in[9];
    const float* mur = (const float*)d_in[10];
    const float* sgr = (const float*)d_in[11];
    const float* wr  = (const float*)d_in[12];
    const float* alpha = (const float*)d_in[13];
    const float* beta  = (const float*)d_in[14];
    const float* gamma = (const float*)d_in[15];

    const int ATTN_SMEM = 25344 * sizeof(float);   // 101376 B
    const int PROJ_SMEM = 2*32*PSS * sizeof(float);// 66560 B
    static bool attr_done = false;
    if (!attr_done){
        cudaFuncSetAttribute(attn_kernel, cudaFuncAttributeMaxDynamicSharedMemorySize, ATTN_SMEM);
        cudaFuncSetAttribute(proj_kernel, cudaFuncAttributeMaxDynamicSharedMemorySize, PROJ_SMEM);
        attr_done = true;
    }

    prep_kernel<<<464, 256>>>(mur,sgr,wr, mua,sga,wa, t, x, WQ, WK, WV);
    grel_kernel<<<2056, 256>>>(t);
    attn_kernel<<<dim3(16, H_, B_), 256, ATTN_SMEM>>>(x, alpha, beta, gamma);
    proj_kernel<<<128, 512, PROJ_SMEM>>>(WO, bO, (float*)d_out);
}

// round 16
// speedup vs baseline: 1.1157x; 1.1157x over previous
#include <cuda_runtime.h>
#include <math.h>

#define B_  2
#define L_  256
#define DM_ 256
#define H_  8
#define DH_ 32
#define T_  4
#define NK_ 4
#define M_  128                 // gaussian terms per (h,t)
#define NPAIR 32896             // L*(L+1)/2, i<=j pairs
#define NTAB 2048
// narrow threshold: sigma < 0.02  <=>  A < -log2e/(2*0.02^2)
#define A_TH (-1803.3688f)
#define KTS 260                 // attn Kt/Xt row stride
#define WSS 36                  // qkv gemm smem row stride (floats, 16B-aligned)
#define PSS 260                 // proj gemm smem row stride (floats, 16B-aligned)

// ---------------- scratch (device globals; no allocation allowed) -------------
__device__ float  g_Q[B_*H_*L_*DH_];
__device__ float  g_K[B_*H_*L_*DH_];
__device__ float  g_V[B_*H_*L_*DH_];
__device__ float4 g_nwP[H_*T_*M_];           // narrow (exact) rel terms, compact per (h,t)
__device__ int    g_ncnt[H_*T_];
__device__ float2 g_tab2[H_*T_*NTAB];        // (f(e), f(e+1)) pairs
__device__ float  g_gabs[B_*H_*L_];
__device__ float  g_grel[B_*H_*L_*L_];
__device__ float  g_outh[B_*L_*DM_];

__device__ __forceinline__ float ex2f(float x){
    float r; asm("ex2.approx.ftz.f32 %0, %1;" : "=f"(r) : "f"(x)); return r;
}
__device__ __forceinline__ void gdc_wait(){
    asm volatile("griddepcontrol.wait;" ::: "memory");
}
__device__ __forceinline__ void gdc_launch(){
    asm volatile("griddepcontrol.launch_dependents;" ::: "memory");
}

// ============ qkv smem GEMM tile: 32 rows x 64 o, 256 threads =================
__device__ __forceinline__ void gemm_tile_32x64(
    const float* __restrict__ Xg, const float* __restrict__ Wg,
    int rbase, int obase, int tid, float* sm, float acc[2][4])
{
    float* xs = sm;                    // [32][WSS]
    float* ws = sm + 32*WSS;           // [64][WSS]
    int o4 = tid & 15, rgrp = tid >> 4;
    int r0 = rgrp*2;
    #pragma unroll
    for (int r=0;r<2;r++)
        #pragma unroll
        for (int c=0;c<4;c++) acc[r][c] = 0.f;

    for (int kt = 0; kt < 8; kt++){
        {
            int r = tid >> 3, kk4 = tid & 7;
            float4 xv = *(const float4*)&Xg[(rbase+r)*DM_ + kt*32 + kk4*4];
            *(float4*)&xs[r*WSS + kk4*4] = xv;
        }
        #pragma unroll
        for (int p2 = 0; p2 < 2; p2++){
            int v = tid + p2*256;
            int oo = v >> 3, kk4 = v & 7;
            float4 wv = *(const float4*)&Wg[(obase+oo)*DM_ + kt*32 + kk4*4];
            *(float4*)&ws[oo*WSS + kk4*4] = wv;
        }
        __syncthreads();
        #pragma unroll
        for (int kk4 = 0; kk4 < 8; kk4++){
            float4 xa = *(const float4*)&xs[r0*WSS + kk4*4];
            float4 xb = *(const float4*)&xs[(r0+1)*WSS + kk4*4];
            #pragma unroll
            for (int c = 0; c < 4; c++){
                float4 w = *(const float4*)&ws[(o4+16*c)*WSS + kk4*4];
                acc[0][c] = fmaf(xa.x,w.x,acc[0][c]);
                acc[0][c] = fmaf(xa.y,w.y,acc[0][c]);
                acc[0][c] = fmaf(xa.z,w.z,acc[0][c]);
                acc[0][c] = fmaf(xa.w,w.w,acc[0][c]);
                acc[1][c] = fmaf(xb.x,w.x,acc[1][c]);
                acc[1][c] = fmaf(xb.y,w.y,acc[1][c]);
                acc[1][c] = fmaf(xb.z,w.z,acc[1][c]);
                acc[1][c] = fmaf(xb.w,w.w,acc[1][c]);
            }
        }
        __syncthreads();
    }
}

// ========== prep: rel-table (bx<256) | gabs (<272) | qkv (<464) ===============
__global__ __launch_bounds__(256) void prep_kernel(
                            const float* __restrict__ mu_r, const float* __restrict__ sg_r,
                            const float* __restrict__ w_r,
                            const float* __restrict__ mu_a, const float* __restrict__ sg_a,
                            const float* __restrict__ w_a,
                            const float* __restrict__ tarr,
                            const float* __restrict__ x,
                            const float* __restrict__ WQ, const float* __restrict__ WK,
                            const float* __restrict__ WV)
{
    __shared__ __align__(16) float sm[32*WSS + 64*WSS];     // 3456 floats
    int bx = blockIdx.x, tid = threadIdx.x;

    if (bx < 256){
        int cx = bx & 7, y = bx >> 3;               // y = h*T+tt
        int h = y >> 2, tt = y & 3;
        float4* Ps = (float4*)sm;                   // 128 float4
        float*  sv = sm + 512;                      // 257 floats
        if (tid < M_){
            int d = tid >> 2, k = tid & 3;
            int src = ((h*DH_+d)*T_+tt)*NK_+k;
            float s = sg_r[src];
            float A = -1.4426950408889634f / (2.0f*s*s);
            Ps[tid] = make_float4(mu_r[src], A, w_r[src], 0.f);
        }
        __syncthreads();
        int e0 = cx*256;
        for (int ee = tid; ee < 257; ee += 256){
            float u = (float)(e0+ee) * (1.0f/NTAB);
            float a0=0.f,a1=0.f,a2=0.f,a3=0.f;
            #pragma unroll 1
            for (int m=0;m<M_;m+=4){
                float4 p0=Ps[m],p1=Ps[m+1],p2=Ps[m+2],p3=Ps[m+3];
                float w0=(p0.y>=A_TH)?p0.z:0.f; float d0=u-p0.x;
                float w1=(p1.y>=A_TH)?p1.z:0.f; float d1=u-p1.x;
                float w2=(p2.y>=A_TH)?p2.z:0.f; float d2=u-p2.x;
                float w3=(p3.y>=A_TH)?p3.z:0.f; float d3=u-p3.x;
                a0 = fmaf(w0, ex2f(d0*d0*p0.y), a0);
                a1 = fmaf(w1, ex2f(d1*d1*p1.y), a1);
                a2 = fmaf(w2, ex2f(d2*d2*p2.y), a2);
                a3 = fmaf(w3, ex2f(d3*d3*p3.y), a3);
            }
            sv[ee] = (a0+a1)+(a2+a3);
        }
        __syncthreads();
        if (e0 + tid < NTAB)
            g_tab2[y*NTAB + e0 + tid] = make_float2(sv[tid], sv[tid+1]);
        if (cx == 0 && tid < 32){
            int base = 0;
            #pragma unroll
            for (int g=0; g<4; g++){
                float4 p = Ps[g*32 + tid];
                bool narrow = (p.y < A_TH);
                unsigned bal = __ballot_sync(0xffffffffu, narrow);
                int pos = __popc(bal & ((1u<<tid)-1u));
                if (narrow) g_nwP[y*M_ + base + pos] = p;
                base += __popc(bal);
            }
            if (tid == 0) g_ncnt[y] = base;
        }
    } else if (bx < 272){
        int y = bx - 256; int h = y >> 1, b = y & 1;
        float4* Ps = (float4*)sm;                   // 512 float4
        for (int pass=0; pass<2; pass++){
            int m2 = pass*256 + tid;
            int tt = m2 >> 7, m = m2 & 127;
            int d = m >> 2, k = m & 3;
            int src = ((h*DH_+d)*T_+tt)*NK_+k;
            float s = sg_a[src];
            float A = -1.4426950408889634f / (2.0f*s*s);
            Ps[m2] = make_float4(mu_a[src], A, w_a[src], 0.f);
        }
        __syncthreads();
        int p = tid;
        float4 tv = *(const float4*)&tarr[(b*L_+p)*T_];
        float us[4] = {tv.x,tv.y,tv.z,tv.w};
        float acc = 0.f;
        #pragma unroll
        for (int tt=0;tt<T_;tt++){
            float u = us[tt];
            const float4* P = Ps + tt*M_;
            #pragma unroll 4
            for (int m=0;m<M_;m++){
                float4 pr = P[m];
                float d = u - pr.x;
                acc = fmaf(pr.z, ex2f(d*d*pr.y), acc);
            }
        }
        g_gabs[(b*H_+h)*L_+p] = acc * (1.0f/DH_);
    } else {
        // ---- qkv GEMM: 192 blocks = 3 mats x 16 rowblocks x 4 ocols ----
        int idx = bx - 272;
        int mat = idx / 64, rem = idx % 64;
        int rbase = (rem >> 2) * 32;
        int obase = (rem & 3) * 64;
        const float* Wm = (mat==0)?WQ:(mat==1)?WK:WV;
        float acc[2][4];
        gemm_tile_32x64(x, Wm, rbase, obase, tid, sm, acc);
        float* dst = (mat==0)?g_Q:(mat==1)?g_K:g_V;
        int o4 = tid & 15, rgrp = tid >> 4;
        #pragma unroll
        for (int r=0;r<2;r++){
            int rg = rbase + rgrp*2 + r;
            int b = rg >> 8, l = rg & 255;
            #pragma unroll
            for (int c=0;c<4;c++){
                int o = obase + o4 + 16*c;
                int h = o >> 5, d = o & 31;
                dst[((b*H_+h)*L_+l)*DH_ + d] = acc[r][c];
            }
        }
    }
}

// ================= grel: 2056 blocks, warp = 32 pairs, uniform h ==============
__global__ __launch_bounds__(256) void grel_kernel(const float* __restrict__ tarr)
{
    __shared__ int ncs[H_*T_];
    int bx = blockIdx.x, tid = threadIdx.x;
    int b  = bx / 1028;
    int pb = bx % 1028;
    if (tid < 32) ncs[tid] = g_ncnt[tid];
    __syncthreads();

    int p = pb*32 + (tid & 31);                 // < 1028*32 = NPAIR exactly
    int h = tid >> 5;
    float disc = sqrtf((float)((2*L_+1)*(2*L_+1) - 8*p));
    int i = (int)((2.0f*L_+1.0f - disc)*0.5f);
    if (i < 0) i = 0; if (i > L_-1) i = L_-1;
    #define TBASE(ii) ((ii)*L_ - ((ii)*((ii)-1))/2)
    while (i+1 <= L_ && TBASE(i+1) <= p) ++i;
    while (TBASE(i) > p) --i;
    int j = i + (p - TBASE(i));
    #undef TBASE

    float4 ti = *(const float4*)&tarr[(b*L_+i)*T_];
    float4 tj = *(const float4*)&tarr[(b*L_+j)*T_];
    float us[4] = {fabsf(ti.x-tj.x), fabsf(ti.y-tj.y), fabsf(ti.z-tj.z), fabsf(ti.w-tj.w)};

    float acc = 0.f;
    #pragma unroll
    for (int tt=0;tt<4;tt++){
        float f = us[tt] * (float)NTAB;
        int ib = (int)f;
        if (ib > NTAB-1) ib = NTAB-1;
        float fr = f - (float)ib;
        float2 v = __ldg(&g_tab2[(h*T_+tt)*NTAB + ib]);
        acc += fmaf(fr, v.y - v.x, v.x);
    }
    #pragma unroll
    for (int tt=0;tt<4;tt++){
        int c = ncs[h*T_+tt];
        const float4* np = g_nwP + (h*T_+tt)*M_;
        for (int m=0; m<c; m++){
            float4 pr = __ldg(&np[m]);
            float d = us[tt] - pr.x;
            acc = fmaf(pr.z, ex2f(d*d*pr.y), acc);
        }
    }
    acc *= (1.0f/DH_);
    g_grel[((b*H_+h)*L_+i)*L_+j] = acc;
    g_grel[((b*H_+h)*L_+j)*L_+i] = acc;
    gdc_launch();                              // release attn (PDL)
}

// ================= fused attention: 16 rows/block, 256 threads ================
__global__ __launch_bounds__(256,2) void attn_kernel(const float* __restrict__ x,
                            const float* __restrict__ alpha,
                            const float* __restrict__ beta,
                            const float* __restrict__ gamma)
{
    extern __shared__ float sm[];
    float* Kt    = sm;              // [32][KTS]  (phase 1)
    float* Xt    = sm + 8320;       // [32][KTS]
    float* Qt    = sm + 16640;      // [32][16]
    float* Vs    = sm + 17152;      // [256][32]
    float* probs = sm;              // [16][256]  (phase 2, aliases Kt)

    int tid = threadIdx.x;
    int i0 = blockIdx.x*16, h = blockIdx.y, b = blockIdx.z;
    const float4* Kg4 = (const float4*)(g_K + (b*H_+h)*L_*DH_);
    const float4* Vg4 = (const float4*)(g_V + (b*H_+h)*L_*DH_);

    // ---- pre-wait phase: loads depend only on prep outputs (already complete)
    for (int v = tid; v < 2048; v += 256){
        int j = v >> 3, d4 = (v & 7)*4;
        float4 kq = Kg4[v];
        Kt[(d4+0)*KTS+j]=kq.x; Kt[(d4+1)*KTS+j]=kq.y; Kt[(d4+2)*KTS+j]=kq.z; Kt[(d4+3)*KTS+j]=kq.w;
        float4 vv = Vg4[v];
        *(float4*)&Vs[j*DH_ + d4] = vv;
        float4 xv = *(const float4*)&x[(b*L_+j)*DM_ + h*DH_ + d4];
        Xt[(d4+0)*KTS+j]=xv.x; Xt[(d4+1)*KTS+j]=xv.y; Xt[(d4+2)*KTS+j]=xv.z; Xt[(d4+3)*KTS+j]=xv.w;
    }
    if (tid < 128){
        int r = tid >> 3, d4 = (tid & 7)*4;
        float4 q = *(const float4*)&g_Q[((b*H_+h)*L_ + i0 + r)*DH_ + d4];
        Qt[(d4+0)*16+r]=q.x; Qt[(d4+1)*16+r]=q.y; Qt[(d4+2)*16+r]=q.z; Qt[(d4+3)*16+r]=q.w;
    }
    __syncthreads();

    int lane = tid & 31, wid = tid >> 5;
    int r0 = (wid & 3)*4;                          // 4 rows of 16
    int jb = (wid >> 2)*128 + lane*4;              // 4 cols of 256

    float sc[4][4], pj[4][4];
    #pragma unroll
    for (int r=0;r<4;r++){
        #pragma unroll
        for (int q=0;q<4;q++){ sc[r][q]=0.f; pj[r][q]=0.f; }
    }
    for (int d=0; d<DH_; d++){
        float4 kv  = *(const float4*)&Kt[d*KTS + jb];
        float4 xv  = *(const float4*)&Xt[d*KTS + jb];
        float4 q4  = *(const float4*)&Qt[d*16 + r0];
        float4 xi4 = *(const float4*)&Xt[d*KTS + i0 + r0];
        float qs[4]  = {q4.x,q4.y,q4.z,q4.w};
        float xis[4] = {xi4.x,xi4.y,xi4.z,xi4.w};
        float kva[4] = {kv.x,kv.y,kv.z,kv.w};
        float xva[4] = {xv.x,xv.y,xv.z,xv.w};
        #pragma unroll
        for (int r=0;r<4;r++){
            #pragma unroll
            for (int q=0;q<4;q++){
                sc[r][q] = fmaf(qs[r],  kva[q], sc[r][q]);
                pj[r][q] = fmaf(xis[r], xva[q], pj[r][q]);
            }
        }
    }

    // ---- PDL barrier: g_grel (from grel_kernel) needed from here on
    gdc_wait();

    float al2 = 2.0f*alpha[h], be = beta[h], ga = gamma[h];
    const float invsq = 0.17677669529663687f;      // 1/sqrt(32)
    float4 ov[4];
    #pragma unroll
    for (int r=0;r<4;r++){
        int ig = i0 + r0 + r;
        float gi = g_gabs[(b*H_+h)*L_ + ig];
        float c0 = al2 * gi;
        float4 gr = *(const float4*)&g_grel[((b*H_+h)*L_ + ig)*L_ + jb];
        ov[r].x = sc[r][0]*invsq*fmaf(pj[r][0], fmaf(be, gr.x, c0), ga);
        ov[r].y = sc[r][1]*invsq*fmaf(pj[r][1], fmaf(be, gr.y, c0), ga);
        ov[r].z = sc[r][2]*invsq*fmaf(pj[r][2], fmaf(be, gr.z, c0), ga);
        ov[r].w = sc[r][3]*invsq*fmaf(pj[r][3], fmaf(be, gr.w, c0), ga);
    }
    __syncthreads();
    #pragma unroll
    for (int r=0;r<4;r++) *(float4*)&probs[(r0+r)*L_ + jb] = ov[r];
    __syncthreads();

    float inv[2];
    #pragma unroll
    for (int rr=0; rr<2; rr++){
        int row = wid*2 + rr;
        float v[8]; float mx = -3.402823466e38f;
        #pragma unroll
        for (int k=0;k<8;k++){ v[k] = probs[row*L_ + k*32 + lane]; mx = fmaxf(mx, v[k]); }
        #pragma unroll
        for (int off=16; off; off>>=1) mx = fmaxf(mx, __shfl_xor_sync(0xffffffffu, mx, off));
        float s = 0.f;
        #pragma unroll
        for (int k=0;k<8;k++){ float e = __expf(v[k]-mx); probs[row*L_ + k*32 + lane] = e; s += e; }
        #pragma unroll
        for (int off=16; off; off>>=1) s += __shfl_xor_sync(0xffffffffu, s, off);
        inv[rr] = 1.0f/s;
    }
    __syncwarp();
    {
        int rbase = wid*2;
        float acc0 = 0.f, acc1 = 0.f;
        for (int j=0; j<L_; j+=4){
            float v0 = Vs[(j+0)*DH_ + lane];
            float v1 = Vs[(j+1)*DH_ + lane];
            float v2 = Vs[(j+2)*DH_ + lane];
            float v3 = Vs[(j+3)*DH_ + lane];
            float4 p0 = *(const float4*)&probs[(rbase+0)*L_ + j];
            float4 p1 = *(const float4*)&probs[(rbase+1)*L_ + j];
            acc0 = fmaf(p0.x, v0, acc0); acc0 = fmaf(p0.y, v1, acc0);
            acc0 = fmaf(p0.z, v2, acc0); acc0 = fmaf(p0.w, v3, acc0);
            acc1 = fmaf(p1.x, v0, acc1); acc1 = fmaf(p1.y, v1, acc1);
            acc1 = fmaf(p1.z, v2, acc1); acc1 = fmaf(p1.w, v3, acc1);
        }
        g_outh[(b*L_ + i0 + rbase+0)*DM_ + h*DH_ + lane] = acc0 * inv[0];
        g_outh[(b*L_ + i0 + rbase+1)*DM_ + h*DH_ + lane] = acc1 * inv[1];
    }
    gdc_launch();                              // release proj (PDL)
}

// ====== output projection: full-K smem GEMM, 512 threads, PDL =================
__global__ __launch_bounds__(512) void proj_kernel(const float* __restrict__ WO,
                                                   const float* __restrict__ bO,
                                                   float* __restrict__ out)
{
    extern __shared__ __align__(16) float psm[];
    float* xs = psm;                   // [32][PSS]
    float* ws = psm + 32*PSS;          // [32][PSS]
    int bx = blockIdx.x, tid = threadIdx.x;
    int rbase = (bx >> 3) * 32;
    int obase = (bx & 7) * 32;

    // pre-wait: WO is a kernel input, always ready
    #pragma unroll
    for (int p = 0; p < 4; p++){
        int v = tid + p*512;
        int r = v >> 6, c4 = v & 63;
        *(float4*)&ws[r*PSS + c4*4] = *(const float4*)&WO[(obase+r)*DM_ + c4*4];
    }
    // PDL barrier: g_outh (from attn) needed from here on
    gdc_wait();
    #pragma unroll
    for (int p = 0; p < 4; p++){
        int v = tid + p*512;
        int r = v >> 6, c4 = v & 63;
        *(float4*)&xs[r*PSS + c4*4] = *(const float4*)&g_outh[(rbase+r)*DM_ + c4*4];
    }
    __syncthreads();

    int o16 = tid & 15, row = tid >> 4;
    const float* xr = &xs[row*PSS];
    const float* wr0 = &ws[o16*PSS];
    const float* wr1 = &ws[(o16+16)*PSS];
    float acc0 = 0.f, acc1 = 0.f;
    #pragma unroll 4
    for (int kk8 = 0; kk8 < 32; kk8++){
        float4 xa0 = *(const float4*)&xr[kk8*8];
        float4 w00 = *(const float4*)&wr0[kk8*8];
        float4 w10 = *(const float4*)&wr1[kk8*8];
        float4 xa1 = *(const float4*)&xr[kk8*8 + 4];
        float4 w01 = *(const float4*)&wr0[kk8*8 + 4];
        float4 w11 = *(const float4*)&wr1[kk8*8 + 4];
        acc0 = fmaf(xa0.x,w00.x,acc0); acc0 = fmaf(xa0.y,w00.y,acc0);
        acc0 = fmaf(xa0.z,w00.z,acc0); acc0 = fmaf(xa0.w,w00.w,acc0);
        acc1 = fmaf(xa0.x,w10.x,acc1); acc1 = fmaf(xa0.y,w10.y,acc1);
        acc1 = fmaf(xa0.z,w10.z,acc1); acc1 = fmaf(xa0.w,w10.w,acc1);
        acc0 = fmaf(xa1.x,w01.x,acc0); acc0 = fmaf(xa1.y,w01.y,acc0);
        acc0 = fmaf(xa1.z,w01.z,acc0); acc0 = fmaf(xa1.w,w01.w,acc0);
        acc1 = fmaf(xa1.x,w11.x,acc1); acc1 = fmaf(xa1.y,w11.y,acc1);
        acc1 = fmaf(xa1.z,w11.z,acc1); acc1 = fmaf(xa1.w,w11.w,acc1);
    }
    int rg = rbase + row;
    int oa = obase + o16, ob = obase + o16 + 16;
    out[rg*DM_ + oa] = acc0 + __ldg(&bO[oa]);
    out[rg*DM_ + ob] = acc1 + __ldg(&bO[ob]);
}

// ================= launch =====================================================
extern "C" void kernel_launch(void* const* d_in, const int* in_sizes, int n_in,
                              void* d_out, int out_size)
{
    const float* x   = (const float*)d_in[0];
    const float* t   = (const float*)d_in[1];
    const float* WQ  = (const float*)d_in[2];
    const float* WK  = (const float*)d_in[3];
    const float* WV  = (const float*)d_in[4];
    const float* WO  = (const float*)d_in[5];
    const float* bO  = (const float*)d_in[6];
    const float* mua = (const float*)d_in[7];
    const float* sga = (const float*)d_in[8];
    const float* wa  = (const float*)d_in[9];
    const float* mur = (const float*)d_in[10];
    const float* sgr = (const float*)d_in[11];
    const float* wr  = (const float*)d_in[12];
    const float* alpha = (const float*)d_in[13];
    const float* beta  = (const float*)d_in[14];
    const float* gamma = (const float*)d_in[15];
    float* outp = (float*)d_out;

    const int ATTN_SMEM = 25344 * sizeof(float);   // 101376 B
    const int PROJ_SMEM = 2*32*PSS * sizeof(float);// 66560 B
    static bool attr_done = false;
    if (!attr_done){
        cudaFuncSetAttribute(attn_kernel, cudaFuncAttributeMaxDynamicSharedMemorySize, ATTN_SMEM);
        cudaFuncSetAttribute(proj_kernel, cudaFuncAttributeMaxDynamicSharedMemorySize, PROJ_SMEM);
        attr_done = true;
    }

    prep_kernel<<<464, 256>>>(mur,sgr,wr, mua,sga,wa, t, x, WQ, WK, WV);
    grel_kernel<<<2056, 256>>>(t);

    cudaLaunchAttribute pdl{};
    pdl.id = cudaLaunchAttributeProgrammaticStreamSerialization;
    pdl.val.programmaticStreamSerializationAllowed = 1;

    {
        cudaLaunchConfig_t cfg{};
        cfg.gridDim = dim3(16, H_, B_);
        cfg.blockDim = dim3(256, 1, 1);
        cfg.dynamicSmemBytes = ATTN_SMEM;
        cfg.stream = 0;
        cfg.attrs = &pdl;
        cfg.numAttrs = 1;
        cudaLaunchKernelEx(&cfg, attn_kernel, x, alpha, beta, gamma);
    }
    {
        cudaLaunchConfig_t cfg{};
        cfg.gridDim = dim3(128, 1, 1);
        cfg.blockDim = dim3(512, 1, 1);
        cfg.dynamicSmemBytes = PROJ_SMEM;
        cfg.stream = 0;
        cfg.attrs = &pdl;
        cfg.numAttrs = 1;
        cudaLaunchKernelEx(&cfg, proj_kernel, WO, bO, outp);
    }
}

// round 17
// speedup vs baseline: 1.1578x; 1.0377x over previous
#include <cuda_runtime.h>
#include <math.h>

#define B_  2
#define L_  256
#define DM_ 256
#define H_  8
#define DH_ 32
#define T_  4
#define NK_ 4
#define M_  128                 // gaussian terms per (h,t)
#define NPAIR 32896             // L*(L+1)/2, i<=j pairs
#define NTAB 2048
// narrow threshold: sigma < 0.02  <=>  A < -log2e/(2*0.02^2)
#define A_TH (-1803.3688f)
#define KTS 260                 // attn Kt/Xt row stride
#define WSS 36                  // qkv gemm smem row stride (floats, 16B-aligned)
#define PSS 260                 // proj gemm smem row stride (floats, 16B-aligned)

// ---------------- scratch (device globals; no allocation allowed) -------------
__device__ float  g_Q[B_*H_*L_*DH_];
__device__ float  g_K[B_*H_*L_*DH_];
__device__ float  g_V[B_*H_*L_*DH_];
__device__ float4 g_nwP[H_*T_*M_];           // narrow (exact) rel terms, compact per (h,t)
__device__ int    g_ncnt[H_*T_];
__device__ float2 g_tab2[H_*T_*NTAB];        // (f(e), f(e+1)) pairs
__device__ float  g_gabs[B_*H_*L_];
__device__ float  g_grel[B_*H_*L_*L_];
__device__ float  g_outh[B_*L_*DM_];

__device__ __forceinline__ float ex2f(float x){
    float r; asm("ex2.approx.ftz.f32 %0, %1;" : "=f"(r) : "f"(x)); return r;
}
__device__ __forceinline__ void gdc_wait(){
    asm volatile("griddepcontrol.wait;" ::: "memory");
}
__device__ __forceinline__ void gdc_launch(){
    asm volatile("griddepcontrol.launch_dependents;" ::: "memory");
}

// ============ qkv smem GEMM tile: 32 rows x 64 o, 256 threads =================
__device__ __forceinline__ void gemm_tile_32x64(
    const float* __restrict__ Xg, const float* __restrict__ Wg,
    int rbase, int obase, int tid, float* sm, float acc[2][4])
{
    float* xs = sm;                    // [32][WSS]
    float* ws = sm + 32*WSS;           // [64][WSS]
    int o4 = tid & 15, rgrp = tid >> 4;
    int r0 = rgrp*2;
    #pragma unroll
    for (int r=0;r<2;r++)
        #pragma unroll
        for (int c=0;c<4;c++) acc[r][c] = 0.f;

    for (int kt = 0; kt < 8; kt++){
        {
            int r = tid >> 3, kk4 = tid & 7;
            float4 xv = *(const float4*)&Xg[(rbase+r)*DM_ + kt*32 + kk4*4];
            *(float4*)&xs[r*WSS + kk4*4] = xv;
        }
        #pragma unroll
        for (int p2 = 0; p2 < 2; p2++){
            int v = tid + p2*256;
            int oo = v >> 3, kk4 = v & 7;
            float4 wv = *(const float4*)&Wg[(obase+oo)*DM_ + kt*32 + kk4*4];
            *(float4*)&ws[oo*WSS + kk4*4] = wv;
        }
        __syncthreads();
        #pragma unroll
        for (int kk4 = 0; kk4 < 8; kk4++){
            float4 xa = *(const float4*)&xs[r0*WSS + kk4*4];
            float4 xb = *(const float4*)&xs[(r0+1)*WSS + kk4*4];
            #pragma unroll
            for (int c = 0; c < 4; c++){
                float4 w = *(const float4*)&ws[(o4+16*c)*WSS + kk4*4];
                acc[0][c] = fmaf(xa.x,w.x,acc[0][c]);
                acc[0][c] = fmaf(xa.y,w.y,acc[0][c]);
                acc[0][c] = fmaf(xa.z,w.z,acc[0][c]);
                acc[0][c] = fmaf(xa.w,w.w,acc[0][c]);
                acc[1][c] = fmaf(xb.x,w.x,acc[1][c]);
                acc[1][c] = fmaf(xb.y,w.y,acc[1][c]);
                acc[1][c] = fmaf(xb.z,w.z,acc[1][c]);
                acc[1][c] = fmaf(xb.w,w.w,acc[1][c]);
            }
        }
        __syncthreads();
    }
}

// ========== prep: rel-table (bx<256) | gabs (<272) | qkv (<464) ===============
__global__ __launch_bounds__(256) void prep_kernel(
                            const float* __restrict__ mu_r, const float* __restrict__ sg_r,
                            const float* __restrict__ w_r,
                            const float* __restrict__ mu_a, const float* __restrict__ sg_a,
                            const float* __restrict__ w_a,
                            const float* __restrict__ tarr,
                            const float* __restrict__ x,
                            const float* __restrict__ WQ, const float* __restrict__ WK,
                            const float* __restrict__ WV)
{
    __shared__ __align__(16) float sm[32*WSS + 64*WSS];     // 3456 floats
    int bx = blockIdx.x, tid = threadIdx.x;

    if (bx < 256){
        int cx = bx & 7, y = bx >> 3;               // y = h*T+tt
        int h = y >> 2, tt = y & 3;
        float4* Ps = (float4*)sm;                   // 128 float4
        float*  sv = sm + 512;                      // 257 floats
        if (tid < M_){
            int d = tid >> 2, k = tid & 3;
            int src = ((h*DH_+d)*T_+tt)*NK_+k;
            float s = sg_r[src];
            float A = -1.4426950408889634f / (2.0f*s*s);
            Ps[tid] = make_float4(mu_r[src], A, w_r[src], 0.f);
        }
        __syncthreads();
        int e0 = cx*256;
        for (int ee = tid; ee < 257; ee += 256){
            float u = (float)(e0+ee) * (1.0f/NTAB);
            float a0=0.f,a1=0.f,a2=0.f,a3=0.f;
            #pragma unroll 1
            for (int m=0;m<M_;m+=4){
                float4 p0=Ps[m],p1=Ps[m+1],p2=Ps[m+2],p3=Ps[m+3];
                float w0=(p0.y>=A_TH)?p0.z:0.f; float d0=u-p0.x;
                float w1=(p1.y>=A_TH)?p1.z:0.f; float d1=u-p1.x;
                float w2=(p2.y>=A_TH)?p2.z:0.f; float d2=u-p2.x;
                float w3=(p3.y>=A_TH)?p3.z:0.f; float d3=u-p3.x;
                a0 = fmaf(w0, ex2f(d0*d0*p0.y), a0);
                a1 = fmaf(w1, ex2f(d1*d1*p1.y), a1);
                a2 = fmaf(w2, ex2f(d2*d2*p2.y), a2);
                a3 = fmaf(w3, ex2f(d3*d3*p3.y), a3);
            }
            sv[ee] = (a0+a1)+(a2+a3);
        }
        __syncthreads();
        if (e0 + tid < NTAB)
            g_tab2[y*NTAB + e0 + tid] = make_float2(sv[tid], sv[tid+1]);
        if (cx == 0 && tid < 32){
            int base = 0;
            #pragma unroll
            for (int g=0; g<4; g++){
                float4 p = Ps[g*32 + tid];
                bool narrow = (p.y < A_TH);
                unsigned bal = __ballot_sync(0xffffffffu, narrow);
                int pos = __popc(bal & ((1u<<tid)-1u));
                if (narrow) g_nwP[y*M_ + base + pos] = p;
                base += __popc(bal);
            }
            if (tid == 0) g_ncnt[y] = base;
        }
    } else if (bx < 272){
        int y = bx - 256; int h = y >> 1, b = y & 1;
        float4* Ps = (float4*)sm;                   // 512 float4
        for (int pass=0; pass<2; pass++){
            int m2 = pass*256 + tid;
            int tt = m2 >> 7, m = m2 & 127;
            int d = m >> 2, k = m & 3;
            int src = ((h*DH_+d)*T_+tt)*NK_+k;
            float s = sg_a[src];
            float A = -1.4426950408889634f / (2.0f*s*s);
            Ps[m2] = make_float4(mu_a[src], A, w_a[src], 0.f);
        }
        __syncthreads();
        int p = tid;
        float4 tv = *(const float4*)&tarr[(b*L_+p)*T_];
        float us[4] = {tv.x,tv.y,tv.z,tv.w};
        float acc = 0.f;
        #pragma unroll
        for (int tt=0;tt<T_;tt++){
            float u = us[tt];
            const float4* P = Ps + tt*M_;
            #pragma unroll 4
            for (int m=0;m<M_;m++){
                float4 pr = P[m];
                float d = u - pr.x;
                acc = fmaf(pr.z, ex2f(d*d*pr.y), acc);
            }
        }
        g_gabs[(b*H_+h)*L_+p] = acc * (1.0f/DH_);
    } else {
        // ---- qkv GEMM: 192 blocks = 3 mats x 16 rowblocks x 4 ocols ----
        int idx = bx - 272;
        int mat = idx / 64, rem = idx % 64;
        int rbase = (rem >> 2) * 32;
        int obase = (rem & 3) * 64;
        const float* Wm = (mat==0)?WQ:(mat==1)?WK:WV;
        float acc[2][4];
        gemm_tile_32x64(x, Wm, rbase, obase, tid, sm, acc);
        float* dst = (mat==0)?g_Q:(mat==1)?g_K:g_V;
        int o4 = tid & 15, rgrp = tid >> 4;
        #pragma unroll
        for (int r=0;r<2;r++){
            int rg = rbase + rgrp*2 + r;
            int b = rg >> 8, l = rg & 255;
            #pragma unroll
            for (int c=0;c<4;c++){
                int o = obase + o4 + 16*c;
                int h = o >> 5, d = o & 31;
                dst[((b*H_+h)*L_+l)*DH_ + d] = acc[r][c];
            }
        }
    }
    gdc_launch();                              // release grel (PDL)
}

// ================= grel: 2056 blocks, warp = 32 pairs, uniform h, PDL =========
__global__ __launch_bounds__(256) void grel_kernel(const float* __restrict__ tarr)
{
    __shared__ int ncs[H_*T_];
    int bx = blockIdx.x, tid = threadIdx.x;
    int b  = bx / 1028;
    int pb = bx % 1028;

    // ---- pre-wait: pair decode + t loads (inputs only) ----
    int p = pb*32 + (tid & 31);                 // < 1028*32 = NPAIR exactly
    int h = tid >> 5;
    float disc = sqrtf((float)((2*L_+1)*(2*L_+1) - 8*p));
    int i = (int)((2.0f*L_+1.0f - disc)*0.5f);
    if (i < 0) i = 0; if (i > L_-1) i = L_-1;
    #define TBASE(ii) ((ii)*L_ - ((ii)*((ii)-1))/2)
    while (i+1 <= L_ && TBASE(i+1) <= p) ++i;
    while (TBASE(i) > p) --i;
    int j = i + (p - TBASE(i));
    #undef TBASE

    float4 ti = *(const float4*)&tarr[(b*L_+i)*T_];
    float4 tj = *(const float4*)&tarr[(b*L_+j)*T_];
    float us[4] = {fabsf(ti.x-tj.x), fabsf(ti.y-tj.y), fabsf(ti.z-tj.z), fabsf(ti.w-tj.w)};

    int   ib[4]; float fr[4];
    #pragma unroll
    for (int tt=0;tt<4;tt++){
        float f = us[tt] * (float)NTAB;
        int ii2 = (int)f;
        if (ii2 > NTAB-1) ii2 = NTAB-1;
        ib[tt] = ii2;
        fr[tt] = f - (float)ii2;
    }

    // ---- PDL barrier: tables/counts from prep needed from here on ----
    gdc_wait();
    if (tid < 32) ncs[tid] = g_ncnt[tid];
    __syncthreads();

    float acc = 0.f;
    #pragma unroll
    for (int tt=0;tt<4;tt++){
        float2 v = __ldg(&g_tab2[(h*T_+tt)*NTAB + ib[tt]]);
        acc += fmaf(fr[tt], v.y - v.x, v.x);
    }
    #pragma unroll
    for (int tt=0;tt<4;tt++){
        int c = ncs[h*T_+tt];
        const float4* np = g_nwP + (h*T_+tt)*M_;
        for (int m=0; m<c; m++){
            float4 pr = __ldg(&np[m]);
            float d = us[tt] - pr.x;
            acc = fmaf(pr.z, ex2f(d*d*pr.y), acc);
        }
    }
    acc *= (1.0f/DH_);
    g_grel[((b*H_+h)*L_+i)*L_+j] = acc;
    g_grel[((b*H_+h)*L_+j)*L_+i] = acc;
    gdc_launch();                              // release attn (PDL)
}

// ================= fused attention: 16 rows/block, 256 threads ================
__global__ __launch_bounds__(256,2) void attn_kernel(const float* __restrict__ x,
                            const float* __restrict__ alpha,
                            const float* __restrict__ beta,
                            const float* __restrict__ gamma)
{
    extern __shared__ float sm[];
    float* Kt    = sm;              // [32][KTS]  (phase 1)
    float* Xt    = sm + 8320;       // [32][KTS]
    float* Qt    = sm + 16640;      // [32][16]
    float* Vs    = sm + 17152;      // [256][32]
    float* probs = sm;              // [16][256]  (phase 2, aliases Kt)

    int tid = threadIdx.x;
    int i0 = blockIdx.x*16, h = blockIdx.y, b = blockIdx.z;
    const float4* Kg4 = (const float4*)(g_K + (b*H_+h)*L_*DH_);
    const float4* Vg4 = (const float4*)(g_V + (b*H_+h)*L_*DH_);

    // ---- pre-wait phase: loads depend only on prep outputs (complete before grel ran)
    for (int v = tid; v < 2048; v += 256){
        int j = v >> 3, d4 = (v & 7)*4;
        float4 kq = Kg4[v];
        Kt[(d4+0)*KTS+j]=kq.x; Kt[(d4+1)*KTS+j]=kq.y; Kt[(d4+2)*KTS+j]=kq.z; Kt[(d4+3)*KTS+j]=kq.w;
        float4 vv = Vg4[v];
        *(float4*)&Vs[j*DH_ + d4] = vv;
        float4 xv = *(const float4*)&x[(b*L_+j)*DM_ + h*DH_ + d4];
        Xt[(d4+0)*KTS+j]=xv.x; Xt[(d4+1)*KTS+j]=xv.y; Xt[(d4+2)*KTS+j]=xv.z; Xt[(d4+3)*KTS+j]=xv.w;
    }
    if (tid < 128){
        int r = tid >> 3, d4 = (tid & 7)*4;
        float4 q = *(const float4*)&g_Q[((b*H_+h)*L_ + i0 + r)*DH_ + d4];
        Qt[(d4+0)*16+r]=q.x; Qt[(d4+1)*16+r]=q.y; Qt[(d4+2)*16+r]=q.z; Qt[(d4+3)*16+r]=q.w;
    }
    __syncthreads();

    int lane = tid & 31, wid = tid >> 5;
    int r0 = (wid & 3)*4;                          // 4 rows of 16
    int jb = (wid >> 2)*128 + lane*4;              // 4 cols of 256

    float sc[4][4], pj[4][4];
    #pragma unroll
    for (int r=0;r<4;r++){
        #pragma unroll
        for (int q=0;q<4;q++){ sc[r][q]=0.f; pj[r][q]=0.f; }
    }
    for (int d=0; d<DH_; d++){
        float4 kv  = *(const float4*)&Kt[d*KTS + jb];
        float4 xv  = *(const float4*)&Xt[d*KTS + jb];
        float4 q4  = *(const float4*)&Qt[d*16 + r0];
        float4 xi4 = *(const float4*)&Xt[d*KTS + i0 + r0];
        float qs[4]  = {q4.x,q4.y,q4.z,q4.w};
        float xis[4] = {xi4.x,xi4.y,xi4.z,xi4.w};
        float kva[4] = {kv.x,kv.y,kv.z,kv.w};
        float xva[4] = {xv.x,xv.y,xv.z,xv.w};
        #pragma unroll
        for (int r=0;r<4;r++){
            #pragma unroll
            for (int q=0;q<4;q++){
                sc[r][q] = fmaf(qs[r],  kva[q], sc[r][q]);
                pj[r][q] = fmaf(xis[r], xva[q], pj[r][q]);
            }
        }
    }

    // ---- PDL barrier: g_grel (from grel_kernel) needed from here on
    gdc_wait();

    float al2 = 2.0f*alpha[h], be = beta[h], ga = gamma[h];
    const float invsq = 0.17677669529663687f;      // 1/sqrt(32)
    float4 ov[4];
    #pragma unroll
    for (int r=0;r<4;r++){
        int ig = i0 + r0 + r;
        float gi = g_gabs[(b*H_+h)*L_ + ig];
        float c0 = al2 * gi;
        float4 gr = *(const float4*)&g_grel[((b*H_+h)*L_ + ig)*L_ + jb];
        ov[r].x = sc[r][0]*invsq*fmaf(pj[r][0], fmaf(be, gr.x, c0), ga);
        ov[r].y = sc[r][1]*invsq*fmaf(pj[r][1], fmaf(be, gr.y, c0), ga);
        ov[r].z = sc[r][2]*invsq*fmaf(pj[r][2], fmaf(be, gr.z, c0), ga);
        ov[r].w = sc[r][3]*invsq*fmaf(pj[r][3], fmaf(be, gr.w, c0), ga);
    }
    __syncthreads();
    #pragma unroll
    for (int r=0;r<4;r++) *(float4*)&probs[(r0+r)*L_ + jb] = ov[r];
    __syncthreads();

    float inv[2];
    #pragma unroll
    for (int rr=0; rr<2; rr++){
        int row = wid*2 + rr;
        float v[8]; float mx = -3.402823466e38f;
        #pragma unroll
        for (int k=0;k<8;k++){ v[k] = probs[row*L_ + k*32 + lane]; mx = fmaxf(mx, v[k]); }
        #pragma unroll
        for (int off=16; off; off>>=1) mx = fmaxf(mx, __shfl_xor_sync(0xffffffffu, mx, off));
        float s = 0.f;
        #pragma unroll
        for (int k=0;k<8;k++){ float e = __expf(v[k]-mx); probs[row*L_ + k*32 + lane] = e; s += e; }
        #pragma unroll
        for (int off=16; off; off>>=1) s += __shfl_xor_sync(0xffffffffu, s, off);
        inv[rr] = 1.0f/s;
    }
    __syncwarp();
    {
        int rbase = wid*2;
        float acc0 = 0.f, acc1 = 0.f;
        for (int j=0; j<L_; j+=4){
            float v0 = Vs[(j+0)*DH_ + lane];
            float v1 = Vs[(j+1)*DH_ + lane];
            float v2 = Vs[(j+2)*DH_ + lane];
            float v3 = Vs[(j+3)*DH_ + lane];
            float4 p0 = *(const float4*)&probs[(rbase+0)*L_ + j];
            float4 p1 = *(const float4*)&probs[(rbase+1)*L_ + j];
            acc0 = fmaf(p0.x, v0, acc0); acc0 = fmaf(p0.y, v1, acc0);
            acc0 = fmaf(p0.z, v2, acc0); acc0 = fmaf(p0.w, v3, acc0);
            acc1 = fmaf(p1.x, v0, acc1); acc1 = fmaf(p1.y, v1, acc1);
            acc1 = fmaf(p1.z, v2, acc1); acc1 = fmaf(p1.w, v3, acc1);
        }
        g_outh[(b*L_ + i0 + rbase+0)*DM_ + h*DH_ + lane] = acc0 * inv[0];
        g_outh[(b*L_ + i0 + rbase+1)*DM_ + h*DH_ + lane] = acc1 * inv[1];
    }
    gdc_launch();                              // release proj (PDL)
}

// ====== output projection: full-K smem GEMM, 512 threads, PDL =================
__global__ __launch_bounds__(512) void proj_kernel(const float* __restrict__ WO,
                                                   const float* __restrict__ bO,
                                                   float* __restrict__ out)
{
    extern __shared__ __align__(16) float psm[];
    float* xs = psm;                   // [32][PSS]
    float* ws = psm + 32*PSS;          // [32][PSS]
    int bx = blockIdx.x, tid = threadIdx.x;
    int rbase = (bx >> 3) * 32;
    int obase = (bx & 7) * 32;

    // pre-wait: WO is a kernel input, always ready
    #pragma unroll
    for (int p = 0; p < 4; p++){
        int v = tid + p*512;
        int r = v >> 6, c4 = v & 63;
        *(float4*)&ws[r*PSS + c4*4] = *(const float4*)&WO[(obase+r)*DM_ + c4*4];
    }
    // PDL barrier: g_outh (from attn) needed from here on
    gdc_wait();
    #pragma unroll
    for (int p = 0; p < 4; p++){
        int v = tid + p*512;
        int r = v >> 6, c4 = v & 63;
        *(float4*)&xs[r*PSS + c4*4] = *(const float4*)&g_outh[(rbase+r)*DM_ + c4*4];
    }
    __syncthreads();

    int o16 = tid & 15, row = tid >> 4;
    const float* xr = &xs[row*PSS];
    const float* wr0 = &ws[o16*PSS];
    const float* wr1 = &ws[(o16+16)*PSS];
    float acc0 = 0.f, acc1 = 0.f;
    #pragma unroll 4
    for (int kk8 = 0; kk8 < 32; kk8++){
        float4 xa0 = *(const float4*)&xr[kk8*8];
        float4 w00 = *(const float4*)&wr0[kk8*8];
        float4 w10 = *(const float4*)&wr1[kk8*8];
        float4 xa1 = *(const float4*)&xr[kk8*8 + 4];
        float4 w01 = *(const float4*)&wr0[kk8*8 + 4];
        float4 w11 = *(const float4*)&wr1[kk8*8 + 4];
        acc0 = fmaf(xa0.x,w00.x,acc0); acc0 = fmaf(xa0.y,w00.y,acc0);
        acc0 = fmaf(xa0.z,w00.z,acc0); acc0 = fmaf(xa0.w,w00.w,acc0);
        acc1 = fmaf(xa0.x,w10.x,acc1); acc1 = fmaf(xa0.y,w10.y,acc1);
        acc1 = fmaf(xa0.z,w10.z,acc1); acc1 = fmaf(xa0.w,w10.w,acc1);
        acc0 = fmaf(xa1.x,w01.x,acc0); acc0 = fmaf(xa1.y,w01.y,acc0);
        acc0 = fmaf(xa1.z,w01.z,acc0); acc0 = fmaf(xa1.w,w01.w,acc0);
        acc1 = fmaf(xa1.x,w11.x,acc1); acc1 = fmaf(xa1.y,w11.y,acc1);
        acc1 = fmaf(xa1.z,w11.z,acc1); acc1 = fmaf(xa1.w,w11.w,acc1);
    }
    int rg = rbase + row;
    int oa = obase + o16, ob = obase + o16 + 16;
    out[rg*DM_ + oa] = acc0 + __ldg(&bO[oa]);
    out[rg*DM_ + ob] = acc1 + __ldg(&bO[ob]);
}

// ================= launch =====================================================
extern "C" void kernel_launch(void* const* d_in, const int* in_sizes, int n_in,
                              void* d_out, int out_size)
{
    const float* x   = (const float*)d_in[0];
    const float* t   = (const float*)d_in[1];
    const float* WQ  = (const float*)d_in[2];
    const float* WK  = (const float*)d_in[3];
    const float* WV  = (const float*)d_in[4];
    const float* WO  = (const float*)d_in[5];
    const float* bO  = (const float*)d_in[6];
    const float* mua = (const float*)d_in[7];
    const float* sga = (const float*)d_in[8];
    const float* wa  = (const float*)d_in[9];
    const float* mur = (const float*)d_in[10];
    const float* sgr = (const float*)d_in[11];
    const float* wr  = (const float*)d_in[12];
    const float* alpha = (const float*)d_in[13];
    const float* beta  = (const float*)d_in[14];
    const float* gamma = (const float*)d_in[15];
    float* outp = (float*)d_out;

    const int ATTN_SMEM = 25344 * sizeof(float);   // 101376 B
    const int PROJ_SMEM = 2*32*PSS * sizeof(float);// 66560 B
    static bool attr_done = false;
    if (!attr_done){
        cudaFuncSetAttribute(attn_kernel, cudaFuncAttributeMaxDynamicSharedMemorySize, ATTN_SMEM);
        cudaFuncSetAttribute(proj_kernel, cudaFuncAttributeMaxDynamicSharedMemorySize, PROJ_SMEM);
        attr_done = true;
    }

    prep_kernel<<<464, 256>>>(mur,sgr,wr, mua,sga,wa, t, x, WQ, WK, WV);

    cudaLaunchAttribute pdl{};
    pdl.id = cudaLaunchAttributeProgrammaticStreamSerialization;
    pdl.val.programmaticStreamSerializationAllowed = 1;

    {
        cudaLaunchConfig_t cfg{};
        cfg.gridDim = dim3(2056, 1, 1);
        cfg.blockDim = dim3(256, 1, 1);
        cfg.dynamicSmemBytes = 0;
        cfg.stream = 0;
        cfg.attrs = &pdl;
        cfg.numAttrs = 1;
        cudaLaunchKernelEx(&cfg, grel_kernel, t);
    }
    {
        cudaLaunchConfig_t cfg{};
        cfg.gridDim = dim3(16, H_, B_);
        cfg.blockDim = dim3(256, 1, 1);
        cfg.dynamicSmemBytes = ATTN_SMEM;
        cfg.stream = 0;
        cfg.attrs = &pdl;
        cfg.numAttrs = 1;
        cudaLaunchKernelEx(&cfg, attn_kernel, x, alpha, beta, gamma);
    }
    {
        cudaLaunchConfig_t cfg{};
        cfg.gridDim = dim3(128, 1, 1);
        cfg.blockDim = dim3(512, 1, 1);
        cfg.dynamicSmemBytes = PROJ_SMEM;
        cfg.stream = 0;
        cfg.attrs = &pdl;
        cfg.numAttrs = 1;
        cudaLaunchKernelEx(&cfg, proj_kernel, WO, bO, outp);
    }
}